// round 9
// baseline (speedup 1.0000x reference)
#include <cuda_runtime.h>
#include <cuda_bf16.h>
#include <math.h>
#include <stdint.h>

#define C_TOT 768
#define HH 180
#define WW 360
#define WF 91          // kept modes along W (of 181)
#define NPOS (HH*WF)   // 16380 positions per channel
#define NBLK 8
#define RB6 6          // rows per block in W kernels

// (cos, sin)(2*pi*j/360)
__device__ float2 d_tw[360];
// scratch spectrum, layout [c][kh][wf<91], complex
__device__ float2 d_freq[(size_t)C_TOT * NPOS];
// real-embedded weights, B^T layout [k][n][kk] row-major (192x192 per block)
__device__ uint16_t d_w1b[NBLK * 192 * 192];
__device__ uint16_t d_w2b[NBLK * 192 * 192];

// compile-time root tables
__device__ constexpr float C12T[12] = {1.f, 0.8660254f, 0.5f, 0.f, -0.5f, -0.8660254f,
                            -1.f, -0.8660254f, -0.5f, 0.f, 0.5f, 0.8660254f};
__device__ constexpr float S12T[12] = {0.f, 0.5f, 0.8660254f, 1.f, 0.8660254f, 0.5f,
                            0.f, -0.5f, -0.8660254f, -1.f, -0.8660254f, -0.5f};
__device__ constexpr float C15T[15] = {1.f, 0.91354546f, 0.66913061f, 0.30901699f, -0.10452846f,
                            -0.5f, -0.80901699f, -0.97814760f, -0.97814760f, -0.80901699f,
                            -0.5f, -0.10452846f, 0.30901699f, 0.66913061f, 0.91354546f};
__device__ constexpr float S15T[15] = {0.f, 0.40673664f, 0.74314483f, 0.95105652f, 0.99452190f,
                            0.86602540f, 0.58778525f, 0.20791169f, -0.20791169f, -0.58778525f,
                            -0.86602540f, -0.99452190f, -0.95105652f, -0.74314483f, -0.40673664f};
__device__ constexpr float C18T[18] = {1.f, 0.93969262f, 0.76604444f, 0.5f, 0.17364818f, -0.17364818f,
                            -0.5f, -0.76604444f, -0.93969262f, -1.f, -0.93969262f, -0.76604444f,
                            -0.5f, -0.17364818f, 0.17364818f, 0.5f, 0.76604444f, 0.93969262f};
__device__ constexpr float S18T[18] = {0.f, 0.34202014f, 0.64278761f, 0.86602540f, 0.98480775f, 0.98480775f,
                            0.86602540f, 0.64278761f, 0.34202014f, 0.f, -0.34202014f, -0.64278761f,
                            -0.86602540f, -0.98480775f, -0.98480775f, -0.86602540f, -0.64278761f, -0.34202014f};
__device__ constexpr float C20T[20] = {1.f, 0.95105652f, 0.80901699f, 0.58778525f, 0.30901699f, 0.f,
                            -0.30901699f, -0.58778525f, -0.80901699f, -0.95105652f, -1.f,
                            -0.95105652f, -0.80901699f, -0.58778525f, -0.30901699f, 0.f,
                            0.30901699f, 0.58778525f, 0.80901699f, 0.95105652f};
__device__ constexpr float S20T[20] = {0.f, 0.30901699f, 0.58778525f, 0.80901699f, 0.95105652f, 1.f,
                            0.95105652f, 0.80901699f, 0.58778525f, 0.30901699f, 0.f,
                            -0.30901699f, -0.58778525f, -0.80901699f, -0.95105652f, -1.f,
                            -0.95105652f, -0.80901699f, -0.58778525f, -0.30901699f};

__global__ void k_init_tw() {
    int j = blockIdx.x * blockDim.x + threadIdx.x;
    if (j < 360) {
        double a = (2.0 * 3.14159265358979323846 / 360.0) * (double)j;
        d_tw[j] = make_float2((float)cos(a), (float)sin(a));
    }
}

// Prep: pack complex weights into real-embedded B^T matrices WT[n][kk]:
// WT[2o][2i]=wr, WT[2o][2i+1]=-wi, WT[2o+1][2i]=wi, WT[2o+1][2i+1]=wr
__global__ void k_prep_w(const float* __restrict__ w1, const float* __restrict__ w2) {
    int k = blockIdx.x;
    uint16_t* o1 = d_w1b + (size_t)k * 192 * 192;
    uint16_t* o2 = d_w2b + (size_t)k * 192 * 192;
    for (int idx = threadIdx.x; idx < 96 * 96; idx += blockDim.x) {
        int i = idx / 96, o = idx % 96;
        #pragma unroll
        for (int L = 0; L < 2; L++) {
            const float* w = (L == 0) ? w1 : w2;
            uint16_t* dst  = (L == 0) ? o1 : o2;
            float wr = w[((k * 96 + i) * 96 + o) * 2 + 0];
            float wi = w[((k * 96 + i) * 96 + o) * 2 + 1];
            dst[(2*o)   * 192 + 2*i]     = __bfloat16_as_ushort(__float2bfloat16( wr));
            dst[(2*o)   * 192 + 2*i + 1] = __bfloat16_as_ushort(__float2bfloat16(-wi));
            dst[(2*o+1) * 192 + 2*i]     = __bfloat16_as_ushort(__float2bfloat16( wi));
            dst[(2*o+1) * 192 + 2*i + 1] = __bfloat16_as_ushort(__float2bfloat16( wr));
        }
    }
}

// ========================= mma.sync helpers ================================
__device__ __forceinline__ uint32_t smem_u32(const void* p) {
    uint32_t a;
    asm("{ .reg .u64 t; cvta.to.shared.u64 t, %1; cvt.u32.u64 %0, t; }" : "=r"(a) : "l"(p));
    return a;
}
#define LDSM_X4(r0, r1, r2, r3, addr) \
    asm volatile("ldmatrix.sync.aligned.m8n8.x4.shared.b16 {%0,%1,%2,%3}, [%4];" \
        : "=r"(r0), "=r"(r1), "=r"(r2), "=r"(r3) : "r"(addr))
#define MMA16816(c, a0, a1, a2, a3, b0, b1) \
    asm volatile("mma.sync.aligned.m16n8k16.row.col.f32.bf16.bf16.f32 " \
        "{%0,%1,%2,%3}, {%4,%5,%6,%7}, {%8,%9}, {%0,%1,%2,%3};" \
        : "+f"((c)[0]), "+f"((c)[1]), "+f"((c)[2]), "+f"((c)[3]) \
        : "r"(a0), "r"(a1), "r"(a2), "r"(a3), "r"(b0), "r"(b1))
#define CP_ASYNC16(dst, src) \
    asm volatile("cp.async.cg.shared.global [%0], [%1], 16;" :: "r"(dst), "l"(src) : "memory")
#define CP_COMMIT() asm volatile("cp.async.commit_group;" ::: "memory")
#define CP_WAIT0()  asm volatile("cp.async.wait_group 0;" ::: "memory")

// ---------------------------------------------------------------------------
// Tensor-core MLP via ldmatrix + mma.sync. CTA = (pos tile 128, block k).
// 512 thr = 16 warps = (8 M-tiles x 2 N-halves). In-place on d_freq.
// smem: A[128][200]bf16 @0 (O1 aliased over it after GEMM1),
//       W1[192][200]bf16 @51200, W2[192][200]bf16 @128000 (cp.async prefetch).
// ---------------------------------------------------------------------------
#define SA   200
#define OFF_A   0
#define OFF_W1  51200
#define OFF_W2  128000
#define MLP_SMEM 204800

__global__ void __launch_bounds__(512, 1) k_mlp_mma(const float* __restrict__ b1,
                                                    const float* __restrict__ b2) {
    extern __shared__ char smem[];
    uint32_t sb = smem_u32(smem);
    int tid = threadIdx.x;
    int w   = tid >> 5, l = tid & 31;
    int mw  = w & 7, nw = w >> 3;
    int m0  = mw * 16;
    int k   = blockIdx.y;
    int p0  = blockIdx.x * 128;
    int nv  = NPOS - p0; if (nv > 128) nv = 128;

    // ---- prefetch W2 (cp.async, consumed only at GEMM2) ----
    {
        const uint4* src = (const uint4*)(d_w2b + (size_t)k * 192 * 192);
        for (int idx = tid; idx < 192 * 24; idx += 512) {
            int r = idx / 24, cc = idx % 24;
            CP_ASYNC16(sb + OFF_W2 + r * 400 + cc * 16, &src[r * 24 + cc]);
        }
        CP_COMMIT();
    }
    // ---- load W1 + A tile ----
    {
        const uint4* src = (const uint4*)(d_w1b + (size_t)k * 192 * 192);
        for (int idx = tid; idx < 192 * 24; idx += 512) {
            int r = idx / 24, cc = idx % 24;
            *(uint4*)(smem + OFF_W1 + r * 400 + cc * 16) = src[r * 24 + cc];
        }
        uint16_t* A = (uint16_t*)(smem + OFF_A);
        for (int idx = tid; idx < 96 * 128; idx += 512) {
            int i = idx >> 7, p = idx & 127;
            float2 v = (p < nv) ? d_freq[(size_t)(k * 96 + i) * NPOS + p0 + p]
                                : make_float2(0.f, 0.f);
            uint32_t u;
            asm("cvt.rn.bf16x2.f32 %0, %1, %2;" : "=r"(u) : "f"(v.y), "f"(v.x));
            *(uint32_t*)&A[p * SA + 2 * i] = u;
        }
    }
    __syncthreads();

    uint32_t aRow = (uint32_t)(m0 + (l & 15));
    uint32_t aOff = (l >> 4) * 8;
    uint32_t wRowB = (uint32_t)(nw * 96 + (l & 15));

    float c[12][4];
    // ---- GEMM1: O1 = relu(A x W1 + b1) ----
    {
        const float2* B1 = (const float2*)b1 + k * 96;
        #pragma unroll
        for (int a = 0; a < 12; a++) {
            int o = nw * 48 + a * 4 + (l & 3);
            float2 bb = __ldg(&B1[o]);
            c[a][0] = bb.x; c[a][1] = bb.y; c[a][2] = bb.x; c[a][3] = bb.y;
        }
        #pragma unroll
        for (int kk = 0; kk < 12; kk++) {
            int k0 = kk * 16;
            uint32_t a0, a1, a2, a3;
            LDSM_X4(a0, a1, a2, a3, sb + OFF_A + (aRow * SA + k0 + aOff) * 2);
            #pragma unroll
            for (int g = 0; g < 6; g++) {
                uint32_t b0, b1r, b2, b3;
                LDSM_X4(b0, b1r, b2, b3,
                        sb + OFF_W1 + ((wRowB + g * 16) * SA + k0 + aOff) * 2);
                MMA16816(c[2 * g],     a0, a1, a2, a3, b0,  b2);
                MMA16816(c[2 * g + 1], a0, a1, a2, a3, b1r, b3);
            }
        }
        // epilogue: relu -> O1 bf16, aliased over A (own M-band only; safe in-warp)
        uint16_t* O1 = (uint16_t*)(smem + OFF_A);
        int p1 = m0 + (l >> 2), p2 = p1 + 8;
        #pragma unroll
        for (int a = 0; a < 12; a++) {
            int n = nw * 96 + a * 8 + (l & 3) * 2;
            uint32_t u;
            float r0 = fmaxf(c[a][0], 0.f), i0 = fmaxf(c[a][1], 0.f);
            float r1 = fmaxf(c[a][2], 0.f), i1 = fmaxf(c[a][3], 0.f);
            asm("cvt.rn.bf16x2.f32 %0, %1, %2;" : "=r"(u) : "f"(i0), "f"(r0));
            *(uint32_t*)&O1[p1 * SA + n] = u;
            asm("cvt.rn.bf16x2.f32 %0, %1, %2;" : "=r"(u) : "f"(i1), "f"(r1));
            *(uint32_t*)&O1[p2 * SA + n] = u;
        }
    }
    CP_WAIT0();
    __syncthreads();

    // ---- GEMM2: out = softshrink(O1 x W2 + b2) ----
    {
        const float2* B2 = (const float2*)b2 + k * 96;
        #pragma unroll
        for (int a = 0; a < 12; a++) {
            int o = nw * 48 + a * 4 + (l & 3);
            float2 bb = __ldg(&B2[o]);
            c[a][0] = bb.x; c[a][1] = bb.y; c[a][2] = bb.x; c[a][3] = bb.y;
        }
        #pragma unroll
        for (int kk = 0; kk < 12; kk++) {
            int k0 = kk * 16;
            uint32_t a0, a1, a2, a3;
            LDSM_X4(a0, a1, a2, a3, sb + OFF_A + (aRow * SA + k0 + aOff) * 2);
            #pragma unroll
            for (int g = 0; g < 6; g++) {
                uint32_t b0, b1r, b2, b3;
                LDSM_X4(b0, b1r, b2, b3,
                        sb + OFF_W2 + ((wRowB + g * 16) * SA + k0 + aOff) * 2);
                MMA16816(c[2 * g],     a0, a1, a2, a3, b0,  b2);
                MMA16816(c[2 * g + 1], a0, a1, a2, a3, b1r, b3);
            }
        }
    }
    __syncthreads();
    // epilogue 2: softshrink -> staging [o][130] float2 at smem base
    {
        float2* outs = (float2*)smem;
        int p1 = m0 + (l >> 2), p2 = p1 + 8;
        #pragma unroll
        for (int a = 0; a < 12; a++) {
            int o = nw * 48 + a * 4 + (l & 3);
            float re = c[a][0], im = c[a][1];
            float vr = fabsf(re) - 0.01f, vi = fabsf(im) - 0.01f;
            re = vr > 0.f ? copysignf(vr, re) : 0.f;
            im = vi > 0.f ? copysignf(vi, im) : 0.f;
            outs[o * 130 + p1] = make_float2(re, im);
            re = c[a][2]; im = c[a][3];
            vr = fabsf(re) - 0.01f; vi = fabsf(im) - 0.01f;
            re = vr > 0.f ? copysignf(vr, re) : 0.f;
            im = vi > 0.f ? copysignf(vi, im) : 0.f;
            outs[o * 130 + p2] = make_float2(re, im);
        }
    }
    __syncthreads();
    {
        const float2* outs = (const float2*)smem;
        for (int idx = tid; idx < 96 * 128; idx += 512) {
            int o = idx >> 7, p = idx & 127;
            if (p < nv)
                d_freq[(size_t)(k * 96 + o) * NPOS + p0 + p] = outs[o * 130 + p];
        }
    }
}

// ---------------------------------------------------------------------------
// Kernel A: rfft along W. 360 = 18*20.
// ---------------------------------------------------------------------------
__global__ __launch_bounds__(128, 6) void k_fwd_w(const float* __restrict__ x) {
    __shared__ float  xs[RB6][WW];
    __shared__ float2 As[20][18][RB6];
    __shared__ float2 tws[360];
    int tid = threadIdx.x;
    size_t row0 = (size_t)blockIdx.x * RB6;
    for (int j = tid; j < 360; j += 128) {
        float2 w = d_tw[j];
        tws[j] = make_float2(w.x, -w.y);
    }
    for (int idx = tid; idx < RB6 * WW; idx += 128)
        xs[idx / WW][idx % WW] = x[row0 * WW + idx];
    __syncthreads();
    if (tid < 18 * RB6) {
        int n2 = tid % 18, r = tid / 18;
        float v[20];
        #pragma unroll
        for (int n1 = 0; n1 < 20; n1++) v[n1] = xs[r][18 * n1 + n2];
        #pragma unroll
        for (int km = 0; km <= 10; km++) {
            float re = 0.f, im = 0.f;
            #pragma unroll
            for (int n1 = 0; n1 < 20; n1++) {
                int m = (n1 * km) % 20;
                re += v[n1] * C20T[m];
                im -= v[n1] * S20T[m];
            }
            As[km][n2][r] = make_float2(re, im);
            if (km >= 1 && km <= 9) As[20 - km][n2][r] = make_float2(re, -im);
        }
    }
    __syncthreads();
    if (tid < 20 * RB6) {
        int km = tid % 20, r = tid / 20;
        float2 B[18];
        int t = 0;
        #pragma unroll
        for (int n2 = 0; n2 < 18; n2++) {
            float2 a = As[km][n2][r];
            float2 w = tws[t];
            B[n2] = make_float2(a.x * w.x - a.y * w.y, a.x * w.y + a.y * w.x);
            t += km; if (t >= 360) t -= 360;
        }
        float2* orow = d_freq + (row0 + r) * WF;
        #pragma unroll
        for (int k2 = 0; k2 < 5; k2++) {
            int k = km + 20 * k2;
            if (k < WF) {
                float xr = 0.f, xi = 0.f;
                #pragma unroll
                for (int n2 = 0; n2 < 18; n2++) {
                    int m = (n2 * k2) % 18;
                    xr += B[n2].x * C18T[m] + B[n2].y * S18T[m];
                    xi += B[n2].y * C18T[m] - B[n2].x * S18T[m];
                }
                orow[k] = make_float2(xr, xi);
            }
        }
    }
}

// ---------------------------------------------------------------------------
// Kernel B/D: complex FFT length 180 along kh. minBlocks=4 for occupancy.
// ---------------------------------------------------------------------------
template <int SGN>
__global__ __launch_bounds__(224, 4) void k_fft_h(float scale) {
    __shared__ float2 in_s[13][HH];
    __shared__ float2 As[13][12][15];
    __shared__ float2 tws[360];
    int tid = threadIdx.x;
    int c   = blockIdx.y;
    int wf0 = blockIdx.x * 13;
    float2* base = d_freq + (size_t)c * NPOS;
    for (int j = tid; j < 360; j += 224) {
        float2 w = d_tw[j];
        tws[j] = make_float2(w.x, SGN < 0 ? -w.y : w.y);
    }
    for (int idx = tid; idx < HH * 13; idx += 224) {
        int kh = idx / 13, col = idx % 13;
        in_s[col][kh] = base[(size_t)kh * WF + wf0 + col];
    }
    __syncthreads();
    if (tid < 15 * 13) {
        int n2 = tid % 15, col = tid / 15;
        float2 v[12];
        #pragma unroll
        for (int n1 = 0; n1 < 12; n1++) v[n1] = in_s[col][15 * n1 + n2];
        #pragma unroll
        for (int km = 0; km < 12; km++) {
            float ar = 0.f, ai = 0.f;
            #pragma unroll
            for (int n1 = 0; n1 < 12; n1++) {
                int m = (n1 * km) % 12;
                float cc = C12T[m];
                float ss = (SGN < 0) ? -S12T[m] : S12T[m];
                ar += v[n1].x * cc - v[n1].y * ss;
                ai += v[n1].x * ss + v[n1].y * cc;
            }
            As[col][km][n2] = make_float2(ar, ai);
        }
    }
    __syncthreads();
    if (tid < 12 * 13) {
        int km = tid % 12, col = tid / 12;
        float2 B[15];
        int t = 0, step = 2 * km;
        #pragma unroll
        for (int n2 = 0; n2 < 15; n2++) {
            float2 a = As[col][km][n2];
            float2 w = tws[t];
            B[n2] = make_float2(a.x * w.x - a.y * w.y, a.x * w.y + a.y * w.x);
            t += step; if (t >= 360) t -= 360;
        }
        #pragma unroll
        for (int k2 = 0; k2 < 15; k2++) {
            float xr = 0.f, xi = 0.f;
            #pragma unroll
            for (int n2 = 0; n2 < 15; n2++) {
                int m = (n2 * k2) % 15;
                float cc = C15T[m];
                float ss = (SGN < 0) ? -S15T[m] : S15T[m];
                xr += B[n2].x * cc - B[n2].y * ss;
                xi += B[n2].x * ss + B[n2].y * cc;
            }
            in_s[col][km + 12 * k2] = make_float2(xr, xi);
        }
    }
    __syncthreads();
    for (int idx = tid; idx < HH * 13; idx += 224) {
        int k = idx / 13, col = idx % 13;
        float2 v = in_s[col][k];
        base[(size_t)k * WF + wf0 + col] = make_float2(v.x * scale, v.y * scale);
    }
}

// ---------------------------------------------------------------------------
// Kernel E: pruned irfft along W + residual.
// ---------------------------------------------------------------------------
__global__ __launch_bounds__(128, 6) void k_inv_w(const float* __restrict__ xin,
                                                  float* __restrict__ outp) {
    __shared__ float2 Xs[RB6][WF + 1];
    __shared__ float2 Ts[18][20][RB6];
    __shared__ float  outs[RB6][WW];
    __shared__ float2 tws[360];
    int tid = threadIdx.x;
    size_t row0 = (size_t)blockIdx.x * RB6;
    const float s = 3.9283710065919305e-3f;
    for (int j = tid; j < 360; j += 128) tws[j] = d_tw[j];
    for (int idx = tid; idx < RB6 * WF; idx += 128) {
        int r = idx / WF, k = idx % WF;
        float2 v = d_freq[(row0 + r) * WF + k];
        float g = (k == 0) ? s : 2.f * s;
        Xs[r][k] = make_float2(v.x * g, v.y * g);
    }
    __syncthreads();
    if (tid < 20 * RB6) {
        int k1 = tid % 20, r = tid / 20;
        float2 v[5];
        #pragma unroll
        for (int k2 = 0; k2 < 5; k2++) {
            int k = k1 + 20 * k2;
            v[k2] = (k < WF) ? Xs[r][k] : make_float2(0.f, 0.f);
        }
        #pragma unroll
        for (int wm = 0; wm < 18; wm++) {
            float tr = 0.f, ti = 0.f;
            #pragma unroll
            for (int k2 = 0; k2 < 5; k2++) {
                int m = (k2 * wm) % 18;
                tr += v[k2].x * C18T[m] - v[k2].y * S18T[m];
                ti += v[k2].x * S18T[m] + v[k2].y * C18T[m];
            }
            Ts[wm][k1][r] = make_float2(tr, ti);
        }
    }
    __syncthreads();
    if (tid < 18 * RB6) {
        int wm = tid % 18, r = tid / 18;
        float2 U[20];
        int t = 0;
        #pragma unroll
        for (int k1 = 0; k1 < 20; k1++) {
            float2 a = Ts[wm][k1][r];
            float2 w = tws[t];
            U[k1] = make_float2(a.x * w.x - a.y * w.y, a.x * w.y + a.y * w.x);
            t += wm; if (t >= 360) t -= 360;
        }
        #pragma unroll
        for (int j = 0; j < 20; j++) {
            float acc = 0.f;
            #pragma unroll
            for (int k1 = 0; k1 < 20; k1++) {
                int m = (k1 * j) % 20;
                acc += U[k1].x * C20T[m] - U[k1].y * S20T[m];
            }
            outs[r][wm + 18 * j] = acc;
        }
    }
    __syncthreads();
    for (int idx = tid; idx < RB6 * WW; idx += 128)
        outp[row0 * WW + idx] = xin[row0 * WW + idx] + outs[idx / WW][idx % WW];
}

// ---------------------------------------------------------------------------
extern "C" void kernel_launch(void* const* d_in, const int* in_sizes, int n_in,
                              void* d_out, int out_size) {
    const float* x  = (const float*)d_in[0];
    const float* w1 = (const float*)d_in[1];
    const float* b1 = (const float*)d_in[2];
    const float* w2 = (const float*)d_in[3];
    const float* b2 = (const float*)d_in[4];
    float* out = (float*)d_out;

    const float s_fwd = 3.9283710065919305e-3f;  // 1/sqrt(64800), ortho fwd

    cudaFuncSetAttribute(k_mlp_mma, cudaFuncAttributeMaxDynamicSharedMemorySize, MLP_SMEM);

    k_init_tw<<<3, 128>>>();
    k_prep_w<<<NBLK, 256>>>(w1, w2);
    k_fwd_w<<<C_TOT * HH / RB6, 128>>>(x);
    k_fft_h<-1><<<dim3(7, C_TOT), 224>>>(s_fwd);  // forward H FFT + ortho norm
    k_mlp_mma<<<dim3(128, NBLK), 512, MLP_SMEM>>>(b1, b2);
    k_fft_h< 1><<<dim3(7, C_TOT), 224>>>(1.f);    // inverse H FFT
    k_inv_w<<<C_TOT * HH / RB6, 128>>>(x, out);
}